// round 8
// baseline (speedup 1.0000x reference)
#include <cuda_runtime.h>
#include <cuda_bf16.h>
#include <cstdint>

// Problem constants
constexpr int B_ = 16, S_ = 512, C_ = 16, D_ = 512;
constexpr float LOG2E = 1.4426950408889634f;

// Scratch (device globals: allocation-free per harness rules)
__device__ unsigned char g_vq[B_ * S_ * D_];           // vis int8 quantized (4 MB)
__device__ unsigned char g_tq[B_ * C_ * S_ * D_];      // text int8, (B,C,S,D) (64 MB)
__device__ __nv_bfloat16 g_vd[B_ * S_ * D_];           // vis normalized bf16 (for diag)
__device__ float g_vs[B_ * S_];                         // vis row scale * LOG2E
__device__ float g_ts[B_ * C_ * S_];                    // text row scale
__device__ float g_rowsum[B_ * C_ * S_];                // per-(b,p) sum_t exp over both halves
__device__ float g_acc[B_ * C_];                        // 0.5 * sum log colsum (partial)
__device__ float g_diag[B_ * C_];                       // sum of diagonal cosines (fp32-ish exact)
__device__ float g_clip[B_ * C_];                       // clip_loss per (b, prompt)

#define DEVFN __device__ __forceinline__

DEVFN float warp_reduce_sum(float v) {
#pragma unroll
    for (int o = 16; o; o >>= 1) v += __shfl_xor_sync(0xffffffffu, v, o);
    return v;
}
DEVFN float warp_reduce_max(float v) {
#pragma unroll
    for (int o = 16; o; o >>= 1) v = fmaxf(v, __shfl_xor_sync(0xffffffffu, v, o));
    return v;
}

DEVFN uint32_t smem_u32(const void* p) { return (uint32_t)__cvta_generic_to_shared(p); }
DEVFN float fast_exp2(float x) { float y; asm("ex2.approx.f32 %0, %1;" : "=f"(y) : "f"(x)); return y; }

DEVFN void cp_async16(uint32_t saddr, const void* gptr) {
    asm volatile("cp.async.cg.shared.global [%0], [%1], 16;" :: "r"(saddr), "l"(gptr));
}
#define CP_COMMIT() asm volatile("cp.async.commit_group;" ::: "memory")
#define CP_WAIT2()  asm volatile("cp.async.wait_group 2;" ::: "memory")
#define CP_WAIT1()  asm volatile("cp.async.wait_group 1;" ::: "memory")
#define CP_WAIT0()  asm volatile("cp.async.wait_group 0;" ::: "memory")

DEVFN void ldsm_x4(uint32_t& r0, uint32_t& r1, uint32_t& r2, uint32_t& r3, uint32_t addr) {
    asm volatile("ldmatrix.sync.aligned.m8n8.x4.shared.b16 {%0,%1,%2,%3}, [%4];"
                 : "=r"(r0), "=r"(r1), "=r"(r2), "=r"(r3) : "r"(addr));
}

DEVFN void imma16832(int* c, const uint32_t* a, const uint32_t* b) {
    asm volatile("mma.sync.aligned.m16n8k32.row.col.s32.s8.s8.s32 "
                 "{%0,%1,%2,%3}, {%4,%5,%6,%7}, {%8,%9}, {%0,%1,%2,%3};"
                 : "+r"(c[0]), "+r"(c[1]), "+r"(c[2]), "+r"(c[3])
                 : "r"(a[0]), "r"(a[1]), "r"(a[2]), "r"(a[3]), "r"(b[0]), "r"(b[1]));
}

// 32B rows, 2x16B chunks; phys chunk = c ^ ((row>>2)&1)  (conflict-free for ldsm + cp.async)
DEVFN uint32_t srow_off(int row, int c) { return (uint32_t)(row * 32 + ((c ^ ((row >> 2) & 1)) << 4)); }

DEVFN uint32_t pack4(int q0, int q1, int q2, int q3) {
    return (uint32_t)(q0 & 255) | ((uint32_t)(q1 & 255) << 8) |
           ((uint32_t)(q2 & 255) << 16) | ((uint32_t)(q3 & 255) << 24);
}

// ---------------------------------------------------------------------------
// Kernel 1: normalize+quantize vis (B,S,D) -> g_vq int8 + g_vs scale (*LOG2E)
// + g_vd bf16 copy for diag. Also zero reduction scratch.
// ---------------------------------------------------------------------------
__global__ void norm_vis_kernel(const float* __restrict__ vis) {
    const int tid = threadIdx.x;
    const int gtid = blockIdx.x * 256 + tid;
    if (gtid < B_ * C_ * S_) g_rowsum[gtid] = 0.f;
    if (gtid < B_ * C_) { g_acc[gtid] = 0.f; g_diag[gtid] = 0.f; }

    int row = blockIdx.x * 8 + (tid >> 5);
    int lane = tid & 31;
    const float4* src = reinterpret_cast<const float4*>(vis + (size_t)row * D_);
    float4 v[4];
    float ss = 0.f, mx = 0.f;
#pragma unroll
    for (int j = 0; j < 4; ++j) {
        v[j] = src[lane + 32 * j];
        ss += v[j].x * v[j].x + v[j].y * v[j].y + v[j].z * v[j].z + v[j].w * v[j].w;
        mx = fmaxf(mx, fmaxf(fmaxf(fabsf(v[j].x), fabsf(v[j].y)),
                             fmaxf(fabsf(v[j].z), fabsf(v[j].w))));
    }
    ss = warp_reduce_sum(ss);
    mx = warp_reduce_max(mx);
    float inv = 1.f / fmaxf(sqrtf(ss), 1e-8f);
    float maxn = fmaxf(mx * inv, 1e-8f);       // max |normalized element|
    float qs = 127.f / maxn;                    // normalized -> int8
    if (lane == 0) g_vs[row] = (maxn * (1.f / 127.f)) * LOG2E;

    uint32_t* qdst = reinterpret_cast<uint32_t*>(g_vq + (size_t)row * D_);
    __nv_bfloat162* bdst = reinterpret_cast<__nv_bfloat162*>(g_vd + (size_t)row * D_);
#pragma unroll
    for (int j = 0; j < 4; ++j) {
        float x0 = v[j].x * inv, x1 = v[j].y * inv, x2 = v[j].z * inv, x3 = v[j].w * inv;
        qdst[lane + 32 * j] = pack4(__float2int_rn(x0 * qs), __float2int_rn(x1 * qs),
                                    __float2int_rn(x2 * qs), __float2int_rn(x3 * qs));
        int c = lane + 32 * j;
        bdst[2 * c]     = __floats2bfloat162_rn(x0, x1);
        bdst[2 * c + 1] = __floats2bfloat162_rn(x2, x3);
    }
}

// ---------------------------------------------------------------------------
// Kernel 2: normalize+quantize text (B,S,C,D) -> g_tq int8 (B,C,S,D) + g_ts;
// accumulate diagonal dot(vd[b,s], tn[b,s,c]) into g_diag.
// ---------------------------------------------------------------------------
__global__ void norm_text_kernel(const float* __restrict__ txt) {
    int row = blockIdx.x * 8 + (threadIdx.x >> 5);     // (b*S + s)*C + c
    int lane = threadIdx.x & 31;
    int pc = row & 15;
    int bs = row >> 4;
    int s = bs & 511;
    int b = bs >> 9;
    int orow = ((b * 16 + pc) << 9) + s;
    const float4* src = reinterpret_cast<const float4*>(txt + (size_t)row * D_);
    float4 v[4];
    float ss = 0.f, mx = 0.f;
#pragma unroll
    for (int j = 0; j < 4; ++j) {
        v[j] = src[lane + 32 * j];
        ss += v[j].x * v[j].x + v[j].y * v[j].y + v[j].z * v[j].z + v[j].w * v[j].w;
        mx = fmaxf(mx, fmaxf(fmaxf(fabsf(v[j].x), fabsf(v[j].y)),
                             fmaxf(fabsf(v[j].z), fabsf(v[j].w))));
    }
    ss = warp_reduce_sum(ss);
    mx = warp_reduce_max(mx);
    float inv = 1.f / fmaxf(sqrtf(ss), 1e-8f);
    float maxn = fmaxf(mx * inv, 1e-8f);
    float qs = 127.f / maxn;
    if (lane == 0) g_ts[orow] = maxn * (1.f / 127.f);

    const __nv_bfloat162* vrow =
        reinterpret_cast<const __nv_bfloat162*>(g_vd + (size_t)(b * S_ + s) * D_);
    float dot = 0.f;
    uint32_t* qdst = reinterpret_cast<uint32_t*>(g_tq + (size_t)orow * D_);
#pragma unroll
    for (int j = 0; j < 4; ++j) {
        int cc = lane + 32 * j;
        float x0 = v[j].x * inv, x1 = v[j].y * inv, x2 = v[j].z * inv, x3 = v[j].w * inv;
        float2 a0 = __bfloat1622float2(vrow[2 * cc]);
        float2 a1 = __bfloat1622float2(vrow[2 * cc + 1]);
        dot += a0.x * x0 + a0.y * x1 + a1.x * x2 + a1.y * x3;
        qdst[cc] = pack4(__float2int_rn(x0 * qs), __float2int_rn(x1 * qs),
                         __float2int_rn(x2 * qs), __float2int_rn(x3 * qs));
    }
    dot = warp_reduce_sum(dot);
    if (lane == 0) atomicAdd(&g_diag[(b << 4) + pc], dot);
}

// ---------------------------------------------------------------------------
// Kernel 3: INT8 GEMM + fused exp/row/col sums. Grid 512: (b,p) x column half.
// Block: 512 vis rows (2 strips of 256) x 256 text cols (4 tiles of 64).
// K=512 as 16 K32-steps per tile -> 128 stages, 4-stage cp.async ring.
// Warp layout 4(m) x 2(n); warp tile 64 x 32. 2 CTAs/SM.
// ---------------------------------------------------------------------------
constexpr uint32_t STAGE_BYTES = 10240;   // A 8192 (256 rows x 32B) + B 2048 (64 x 32B)
constexpr uint32_t OFF_ROW = 40960;       // 512 f32
constexpr uint32_t OFF_COL = 43008;       // 256 f32
constexpr uint32_t OFF_SVL = 44032;       // 512 f32 (vis scales * LOG2E)
constexpr uint32_t OFF_STC = 46080;       // 256 f32 (text scales, this half)
constexpr uint32_t OFF_RED = 47104;       // 8 f32
constexpr uint32_t DYN_BYTES = 47136 + 1024;

extern __shared__ char dynsmem[];

__global__ __launch_bounds__(256, 2) void clip_gemm_kernel() {
    const int tid = threadIdx.x, lane = tid & 31, warp = tid >> 5;
    const int wm = warp & 3;        // rows wm*64
    const int wn = warp >> 2;       // cols wn*32
    const int bid = blockIdx.x;
    const int bp = bid >> 1;        // b*16 + p
    const int ch = bid & 1;         // column half

    const char* Agc = reinterpret_cast<const char*>(g_vq) + (size_t)(bp >> 4) * (S_ * D_);
    const char* Bgc = reinterpret_cast<const char*>(g_tq) + (size_t)bp * (S_ * D_)
                                                          + (size_t)ch * 256 * D_;

    const uint32_t raw = smem_u32(dynsmem);
    const uint32_t sbase = (raw + 1023u) & ~1023u;
    char* gb = dynsmem + (sbase - raw);
    float* s_rowsum = (float*)(gb + OFF_ROW);
    float* s_colsum = (float*)(gb + OFF_COL);
    float* s_svl    = (float*)(gb + OFF_SVL);
    float* s_stc    = (float*)(gb + OFF_STC);
    float* s_red    = (float*)(gb + OFF_RED);

    s_rowsum[tid] = 0.f; s_rowsum[tid + 256] = 0.f;
    s_colsum[tid & 255] = 0.f;
    s_svl[tid] = g_vs[(bp >> 4) * 512 + tid];
    s_svl[tid + 256] = g_vs[(bp >> 4) * 512 + tid + 256];
    if (tid < 256) s_stc[tid] = g_ts[bp * 512 + ch * 256 + tid];

    // ldmatrix relative offsets (within a stage)
    uint32_t aoffr[4], boffr[2];
    {
        int r16 = lane & 15, ca = lane >> 4;
#pragma unroll
        for (int mi = 0; mi < 4; ++mi)
            aoffr[mi] = srow_off(wm * 64 + mi * 16 + r16, ca);
        int rb = (lane & 7) + ((lane >> 4) << 3);
        int cb = (lane >> 3) & 1;
#pragma unroll
        for (int nj = 0; nj < 2; ++nj)
            boffr[nj] = 8192u + srow_off(wn * 32 + nj * 16 + rb, cb);
    }

    // per-thread cp.async assignments
    const int ar0 = tid >> 1, ac0 = tid & 1;          // A chunk pair (j=0,1 adds 256 to ci)
    const int br  = tid >> 1, bc = tid & 1;           // B (tid < 128 only)

    // stage st -> strip = st>>6 (A rows), tt = (st>>4)&3 (B rows), kk = st&15
    auto load_stage = [&](int st) {
        const uint32_t base = sbase + (uint32_t)(st & 3) * STAGE_BYTES;
        const char* Ap = Agc + (st >> 6) * (256 * 512) + (st & 15) * 32;
        const char* Bp = Bgc + ((st >> 4) & 3) * (64 * 512) + (st & 15) * 32;
        cp_async16(base + srow_off(ar0, ac0), Ap + ar0 * 512 + ac0 * 16);
        cp_async16(base + srow_off(ar0 + 128, ac0), Ap + (ar0 + 128) * 512 + ac0 * 16);
        if (tid < 128)
            cp_async16(base + 8192u + srow_off(br, bc), Bp + br * 512 + bc * 16);
        CP_COMMIT();
    };

    int acc[4][4][4];
#pragma unroll
    for (int mi = 0; mi < 4; ++mi)
#pragma unroll
        for (int nj = 0; nj < 4; ++nj)
#pragma unroll
            for (int e = 0; e < 4; ++e) acc[mi][nj][e] = 0;
    float rowpart[8];
#pragma unroll
    for (int i = 0; i < 8; ++i) rowpart[i] = 0.f;

    __syncthreads();   // scale/zero smem init visible before epilogue use

    load_stage(0); load_stage(1); load_stage(2);

#pragma unroll 1
    for (int st = 0; st < 128; ++st) {
        if (st < 126) { CP_WAIT2(); } else if (st == 126) { CP_WAIT1(); } else { CP_WAIT0(); }
        __syncthreads();
        if (st + 3 < 128) load_stage(st + 3);

        const uint32_t base = sbase + (uint32_t)(st & 3) * STAGE_BYTES;
        uint32_t af[4][4], bfr[2][4];
#pragma unroll
        for (int mi = 0; mi < 4; ++mi)
            ldsm_x4(af[mi][0], af[mi][1], af[mi][2], af[mi][3], base + aoffr[mi]);
#pragma unroll
        for (int nj = 0; nj < 2; ++nj)
            ldsm_x4(bfr[nj][0], bfr[nj][1], bfr[nj][2], bfr[nj][3], base + boffr[nj]);
#pragma unroll
        for (int mi = 0; mi < 4; ++mi)
#pragma unroll
            for (int n8 = 0; n8 < 4; ++n8)
                imma16832(acc[mi][n8], af[mi], &bfr[n8 >> 1][(n8 & 1) * 2]);

        if ((st & 15) == 15) {
            const int tt = (st >> 4) & 3;
            const int strip = st >> 6;
            const int r0 = lane >> 2, c0 = (lane & 3) * 2;
            // row/col scales for this warp's fragment rows/cols
            float rs[8], cs[8];
#pragma unroll
            for (int i = 0; i < 8; ++i) {
                rs[i] = s_svl[strip * 256 + wm * 64 + (i >> 1) * 16 + (i & 1) * 8 + r0];
                cs[i] = s_stc[tt * 64 + wn * 32 + (i >> 1) * 8 + (i & 1) + c0];
            }
            float colpart[8];
#pragma unroll
            for (int i = 0; i < 8; ++i) colpart[i] = 0.f;
#pragma unroll
            for (int mi = 0; mi < 4; ++mi)
#pragma unroll
                for (int n8 = 0; n8 < 4; ++n8)
#pragma unroll
                    for (int e = 0; e < 4; ++e) {
                        int ri = mi * 2 + (e >> 1);
                        int ci = n8 * 2 + (e & 1);
                        float val = __int2float_rn(acc[mi][n8][e]) * rs[ri] * cs[ci];
                        float ex = fast_exp2(val);
                        rowpart[ri] += ex;
                        colpart[ci] += ex;
                        acc[mi][n8][e] = 0;
                    }
#pragma unroll
            for (int off = 4; off < 32; off <<= 1)
#pragma unroll
                for (int i = 0; i < 8; ++i)
                    colpart[i] += __shfl_xor_sync(0xffffffffu, colpart[i], off);
            if (lane < 4) {
                const int tb = tt * 64 + wn * 32;
#pragma unroll
                for (int i = 0; i < 8; ++i)
                    atomicAdd(&s_colsum[tb + (i >> 1) * 8 + (i & 1) + lane * 2], colpart[i]);
            }
            if ((st & 63) == 63) {
#pragma unroll
                for (int off = 1; off < 4; off <<= 1)
#pragma unroll
                    for (int i = 0; i < 8; ++i)
                        rowpart[i] += __shfl_xor_sync(0xffffffffu, rowpart[i], off);
                if ((lane & 3) == 0) {
#pragma unroll
                    for (int i = 0; i < 8; ++i) {
                        int v = strip * 256 + wm * 64 + (i >> 1) * 16 + (i & 1) * 8 + (lane >> 2);
                        atomicAdd(&s_rowsum[v], rowpart[i]);
                    }
                }
#pragma unroll
                for (int i = 0; i < 8; ++i) rowpart[i] = 0.f;
            }
        }
    }
    __syncthreads();

    // flush rowsum to global; colsum -> 0.5 * sum(log) scalar
    atomicAdd(&g_rowsum[bp * 512 + tid], s_rowsum[tid]);
    atomicAdd(&g_rowsum[bp * 512 + tid + 256], s_rowsum[tid + 256]);

    float lc = logf(s_colsum[tid & 255]);
    if (tid >= 256) lc = 0.f;
    lc = warp_reduce_sum(lc);
    if (lane == 0) s_red[warp] = lc;
    __syncthreads();
    if (tid == 0) {
        float tot = 0.f;
#pragma unroll
        for (int w = 0; w < 8; ++w) tot += s_red[w];
        atomicAdd(&g_acc[bp], 0.5f * tot);
    }
}

// ---------------------------------------------------------------------------
// Kernel 4: clip_reduce. clip[bp] = (0.5*sum log rowsum + g_acc - g_diag)/512
// ---------------------------------------------------------------------------
__global__ void clip_reduce_kernel() {
    const int bp = blockIdx.x, tid = threadIdx.x;   // 128 threads
    float s = 0.f;
#pragma unroll
    for (int i = 0; i < 4; ++i) s += logf(g_rowsum[bp * 512 + tid + i * 128]);
    s = warp_reduce_sum(s);
    __shared__ float sr[4];
    if ((tid & 31) == 0) sr[tid >> 5] = s;
    __syncthreads();
    if (tid == 0) {
        float tot = sr[0] + sr[1] + sr[2] + sr[3];
        g_clip[bp] = (0.5f * tot + g_acc[bp] - g_diag[bp]) * (1.0f / 512.0f);
    }
}

// ---------------------------------------------------------------------------
// Kernel 5: finalize. loss = mean((output-clip)^2); acc; preds broadcast.
// ---------------------------------------------------------------------------
__global__ void finalize_kernel(const float* __restrict__ output,
                                float* __restrict__ out, int out_size) {
    __shared__ float s_sq[8];
    __shared__ int s_pred[16];
    __shared__ int s_match;
    const int tid = threadIdx.x;
    const int lane = tid & 31, warp = tid >> 5;
    if (tid == 0) s_match = 0;
    __syncthreads();

    float d = output[tid] - g_clip[tid];
    float sq = warp_reduce_sum(d * d);
    if (lane == 0) s_sq[warp] = sq;

    if (tid < 16) {
        int b = tid;
        float bo = output[b * 16], bc = g_clip[b * 16];
        int po = 0, pcidx = 0;
#pragma unroll
        for (int c = 1; c < 16; ++c) {
            float o = output[b * 16 + c];
            if (o < bo) { bo = o; po = c; }
            float cl = g_clip[b * 16 + c];
            if (cl < bc) { bc = cl; pcidx = c; }
        }
        s_pred[b] = po;
        if (po == pcidx) atomicAdd(&s_match, 1);
    }
    __syncthreads();

    if (tid == 0) {
        float tot = 0.f;
#pragma unroll
        for (int w = 0; w < 8; ++w) tot += s_sq[w];
        if (out_size > 0) out[0] = tot * (1.0f / 256.0f);
        if (out_size > 1) out[1] = (float)s_match * (100.0f / 16.0f);
    }
    for (int idx = tid; idx < 8192; idx += 256) {
        int b = idx >> 9;
        if (idx + 2 < out_size) out[idx + 2] = (float)s_pred[b];
    }
}

// ---------------------------------------------------------------------------
extern "C" void kernel_launch(void* const* d_in, const int* in_sizes, int n_in,
                              void* d_out, int out_size) {
    const float* output = (const float*)d_in[0];        // (B, C)
    const float* text   = (const float*)d_in[1];        // (B, S, C, D)
    const float* vis    = (const float*)d_in[2];        // (B, S, D)
    float* out = (float*)d_out;

    cudaFuncSetAttribute(clip_gemm_kernel, cudaFuncAttributeMaxDynamicSharedMemorySize, DYN_BYTES);

    norm_vis_kernel<<<(B_ * S_) / 8, 256>>>(vis);
    norm_text_kernel<<<(B_ * S_ * C_) / 8, 256>>>(text);
    clip_gemm_kernel<<<2 * B_ * C_, 256, DYN_BYTES>>>();
    clip_reduce_kernel<<<B_ * C_, 128>>>();
    finalize_kernel<<<1, 256>>>(output, out, out_size);
}

// round 13
// speedup vs baseline: 2.1199x; 2.1199x over previous
#include <cuda_runtime.h>
#include <cuda_bf16.h>
#include <cstdint>

// Problem constants
constexpr int B_ = 16, S_ = 512, C_ = 16, D_ = 512;
constexpr float LOG2E = 1.4426950408889634f;
constexpr float LN2   = 0.6931471805599453f;

// Scratch (device globals: allocation-free per harness rules)
__device__ __nv_bfloat16 g_vn[B_ * S_ * D_];          // normalized vis * log2e, bf16 (8 MB)
__device__ __nv_bfloat16 g_tn[B_ * C_ * S_ * D_];     // normalized text, (B,C,S,D), bf16 (128 MB)
__device__ float g_rowsum[B_ * C_ * S_];               // per-(b,p) rowsum over v
__device__ float g_acc[B_ * C_];                       // 0.5 * sum log colsum (partial)
__device__ float g_diag[B_ * C_];                      // sum of diagonal cosines
__device__ float g_clip[B_ * C_];                      // clip_loss per (b, prompt)

#define DEVFN __device__ __forceinline__

DEVFN float warp_reduce_sum(float v) {
#pragma unroll
    for (int o = 16; o; o >>= 1) v += __shfl_xor_sync(0xffffffffu, v, o);
    return v;
}

DEVFN uint32_t smem_u32(const void* p) { return (uint32_t)__cvta_generic_to_shared(p); }
DEVFN float fast_exp2(float x) { float y; asm("ex2.approx.f32 %0, %1;" : "=f"(y) : "f"(x)); return y; }

DEVFN void cp_async16(uint32_t saddr, const void* gptr) {
    asm volatile("cp.async.cg.shared.global [%0], [%1], 16;" :: "r"(saddr), "l"(gptr));
}
#define CP_COMMIT() asm volatile("cp.async.commit_group;" ::: "memory")
#define CP_WAIT1()  asm volatile("cp.async.wait_group 1;" ::: "memory")
#define CP_WAIT0()  asm volatile("cp.async.wait_group 0;" ::: "memory")

DEVFN void ldsm_x4(uint32_t& r0, uint32_t& r1, uint32_t& r2, uint32_t& r3, uint32_t addr) {
    asm volatile("ldmatrix.sync.aligned.m8n8.x4.shared.b16 {%0,%1,%2,%3}, [%4];"
                 : "=r"(r0), "=r"(r1), "=r"(r2), "=r"(r3) : "r"(addr));
}

DEVFN void mma16816(float* c, const uint32_t* a, const uint32_t* b) {
    asm volatile("mma.sync.aligned.m16n8k16.row.col.f32.bf16.bf16.f32 "
                 "{%0,%1,%2,%3}, {%4,%5,%6,%7}, {%8,%9}, {%0,%1,%2,%3};"
                 : "+f"(c[0]), "+f"(c[1]), "+f"(c[2]), "+f"(c[3])
                 : "r"(a[0]), "r"(a[1]), "r"(a[2]), "r"(a[3]), "r"(b[0]), "r"(b[1]));
}

// swizzle: 64B rows, 4x16B chunks; phys_chunk = kb ^ ((row>>1)&3)
DEVFN int swz(int row, int kb) { return kb ^ ((row >> 1) & 3); }

// ---------------------------------------------------------------------------
// Kernel 1: normalize vis (B,S,D) -> g_vn bf16 scaled by log2e; zero scratch.
// ---------------------------------------------------------------------------
__global__ void norm_vis_kernel(const float* __restrict__ vis) {
    const int tid = threadIdx.x;
    const int gtid = blockIdx.x * 256 + tid;
    if (gtid < B_ * C_ * S_) g_rowsum[gtid] = 0.f;
    if (gtid < B_ * C_) { g_acc[gtid] = 0.f; g_diag[gtid] = 0.f; }

    int row = blockIdx.x * 8 + (tid >> 5);
    int lane = tid & 31;
    const float4* src = reinterpret_cast<const float4*>(vis + (size_t)row * D_);
    float4 v[4];
    float ss = 0.f;
#pragma unroll
    for (int j = 0; j < 4; ++j) {
        v[j] = src[lane + 32 * j];
        ss += v[j].x * v[j].x + v[j].y * v[j].y + v[j].z * v[j].z + v[j].w * v[j].w;
    }
    ss = warp_reduce_sum(ss);
    float inv = LOG2E / fmaxf(sqrtf(ss), 1e-8f);
    __nv_bfloat162* dst = reinterpret_cast<__nv_bfloat162*>(g_vn + (size_t)row * D_);
#pragma unroll
    for (int j = 0; j < 4; ++j) {
        int c = lane + 32 * j;
        dst[2 * c]     = __floats2bfloat162_rn(v[j].x * inv, v[j].y * inv);
        dst[2 * c + 1] = __floats2bfloat162_rn(v[j].z * inv, v[j].w * inv);
    }
}

// ---------------------------------------------------------------------------
// Kernel 2: GEMM + fused text-normalization prologue + exp/row/col sums.
// Grid 512: (b,p) x text-half. Each block OWNS its 256 text rows:
//   prologue: read raw fp32 text rows, l2-normalize, cast bf16 -> g_tn,
//             accumulate diagonal dots; __syncthreads makes the stores
//             visible to this block's own cp.async reads (L2-hot).
//   mainloop: R7 pipeline: 512 vis rows (2 strips of 256) x 256 text cols
//             (4 tiles of 64), 128 K32 stages, 3-stage cp.async ring,
//             warp layout 4(m) x 2(n), 2 CTAs/SM.
// ---------------------------------------------------------------------------
constexpr uint32_t SA_BYTES = 16384;   // 256 rows x 64B (K32, SW)
constexpr uint32_t SB_BYTES = 4096;    // 64 rows x 64B
constexpr uint32_t OFF_A   = 0;        // 3 stages
constexpr uint32_t OFF_B   = 49152;    // 3 stages
constexpr uint32_t OFF_ROW = 61440;    // 512 f32
constexpr uint32_t OFF_COL = 63488;    // 256 f32
constexpr uint32_t OFF_RED = 64512;    // 8 f32
constexpr uint32_t DYN_BYTES = 64544 + 1024;

extern __shared__ char dynsmem[];

__global__ __launch_bounds__(256, 2) void clip_gemm_kernel(const float* __restrict__ txt) {
    const int tid = threadIdx.x, lane = tid & 31, warp = tid >> 5;
    const int wm = warp & 3;        // rows wm*64
    const int wn = warp >> 2;       // cols wn*32
    const int bid = blockIdx.x;
    const int bp = bid >> 1;        // b*16 + p
    const int ch = bid & 1;         // text-row half
    const int b = bp >> 4, p = bp & 15;

    const char* Agc = reinterpret_cast<const char*>(g_vn + (size_t)b * (S_ * D_));
    const char* Bgc = reinterpret_cast<const char*>(g_tn + (size_t)bp * (S_ * D_)
                                                    + (size_t)ch * 256 * D_);

    const uint32_t raw = smem_u32(dynsmem);
    const uint32_t sbase = (raw + 1023u) & ~1023u;
    char* gb = dynsmem + (sbase - raw);
    float* s_rowsum = (float*)(gb + OFF_ROW);
    float* s_colsum = (float*)(gb + OFF_COL);
    float* s_red    = (float*)(gb + OFF_RED);

    s_rowsum[tid] = 0.f; s_rowsum[tid + 256] = 0.f;
    s_colsum[tid & 255] = 0.f;

    // ---- Prologue: normalize this block's 256 text rows (fp32 -> bf16) ----
    {
        float diag_acc = 0.f;
#pragma unroll 1
        for (int i = 0; i < 32; ++i) {
            int sl = warp * 32 + i;                    // local text row 0..255
            int s = ch * 256 + sl;                     // sequence position
            const float4* src = reinterpret_cast<const float4*>(
                txt + ((size_t)((b * S_ + s) * C_) + p) * D_);
            float4 v[4];
            float ss = 0.f;
#pragma unroll
            for (int j = 0; j < 4; ++j) {
                v[j] = src[lane + 32 * j];
                ss += v[j].x * v[j].x + v[j].y * v[j].y + v[j].z * v[j].z + v[j].w * v[j].w;
            }
            ss = warp_reduce_sum(ss);
            float inv = 1.f / fmaxf(sqrtf(ss), 1e-8f);

            const __nv_bfloat162* vrow =
                reinterpret_cast<const __nv_bfloat162*>(g_vn + (size_t)(b * S_ + s) * D_);
            float dot = 0.f;
            __nv_bfloat162* dst = reinterpret_cast<__nv_bfloat162*>(
                g_tn + ((size_t)bp * S_ + s) * D_);
#pragma unroll
            for (int j = 0; j < 4; ++j) {
                int cc = lane + 32 * j;
                float x0 = v[j].x * inv, x1 = v[j].y * inv;
                float x2 = v[j].z * inv, x3 = v[j].w * inv;
                float2 a0 = __bfloat1622float2(vrow[2 * cc]);
                float2 a1 = __bfloat1622float2(vrow[2 * cc + 1]);
                dot += a0.x * x0 + a0.y * x1 + a1.x * x2 + a1.y * x3;
                dst[2 * cc]     = __floats2bfloat162_rn(x0, x1);
                dst[2 * cc + 1] = __floats2bfloat162_rn(x2, x3);
            }
            diag_acc += dot;   // (g_vn carries LOG2E; rescale below)
        }
        diag_acc = warp_reduce_sum(diag_acc);
        if (lane == 0) atomicAdd(&g_diag[bp], diag_acc * LN2);
    }
    __syncthreads();   // text rows + smem zeros visible before cp.async reads

    // ---- Per-thread cp.async offsets. A: 4 chunks of 16B; B: 1 chunk. ----
    uint32_t aG[4], aD[4];
#pragma unroll
    for (int j = 0; j < 4; ++j) {
        int row = (tid >> 2) + 64 * j;
        int kb = tid & 3;
        aG[j] = (uint32_t)(row * 1024 + kb * 16);
        aD[j] = (uint32_t)((row * 32 + swz(row, kb) * 8) * 2);
    }
    const int rowb = tid >> 2, kbb = tid & 3;
    const uint32_t bG = (uint32_t)(rowb * 1024 + kbb * 16);
    const uint32_t bD = (uint32_t)((rowb * 32 + swz(rowb, kbb) * 8) * 2);

    // ldmatrix byte offsets within a stage
    uint32_t aoff[4][2], boff[2][2];
    {
        int r16 = lane & 15;
        int koff = lane >> 4;
#pragma unroll
        for (int mi = 0; mi < 4; ++mi) {
            int r = wm * 64 + mi * 16 + r16;
#pragma unroll
            for (int ks = 0; ks < 2; ++ks) {
                int chk = ks * 2 + koff;
                aoff[mi][ks] = (uint32_t)((r * 32 + swz(r, chk) * 8) * 2);
            }
        }
        int rb8 = (lane & 7) + ((lane >> 4) << 3);
        int kob = (lane >> 3) & 1;
#pragma unroll
        for (int nj = 0; nj < 2; ++nj) {
            int r = wn * 32 + nj * 16 + rb8;
#pragma unroll
            for (int ks = 0; ks < 2; ++ks) {
                int chk = ks * 2 + kob;
                boff[nj][ks] = (uint32_t)((r * 32 + swz(r, chk) * 8) * 2);
            }
        }
    }

    uint32_t A0 = sbase + OFF_A,  A1 = A0 + SA_BYTES,  A2 = A1 + SA_BYTES;
    uint32_t Bb0 = sbase + OFF_B, Bb1 = Bb0 + SB_BYTES, Bb2 = Bb1 + SB_BYTES;

    // stage st -> strip = st>>6, tt = (st>>4)&3, kk = st&15
    auto load_stage = [&](int st, uint32_t sA, uint32_t sB) {
        const char* Ap = Agc + (st >> 6) * 262144 + (st & 15) * 64;
        const char* Bp = Bgc + ((st >> 4) & 3) * 65536 + (st & 15) * 64;
#pragma unroll
        for (int j = 0; j < 4; ++j) cp_async16(sA + aD[j], Ap + aG[j]);
        cp_async16(sB + bD, Bp + bG);
    };

    float acc[4][4][4];
#pragma unroll
    for (int mi = 0; mi < 4; ++mi)
#pragma unroll
        for (int nj = 0; nj < 4; ++nj)
#pragma unroll
            for (int e = 0; e < 4; ++e) acc[mi][nj][e] = 0.f;
    float rowpart[8];
#pragma unroll
    for (int i = 0; i < 8; ++i) rowpart[i] = 0.f;

    // prologue loads
    load_stage(0, A0, Bb0); CP_COMMIT();
    load_stage(1, A1, Bb1); CP_COMMIT();

#pragma unroll 1
    for (int st = 0; st < 128; ++st) {
        if (st < 127) { CP_WAIT1(); } else { CP_WAIT0(); }
        __syncthreads();
        if (st + 2 < 128) { load_stage(st + 2, A2, Bb2); CP_COMMIT(); }

        // compute stage st (buffers A0/Bb0)
#pragma unroll
        for (int ks = 0; ks < 2; ++ks) {
            uint32_t af[4][4], bf[2][4];
#pragma unroll
            for (int mi = 0; mi < 4; ++mi)
                ldsm_x4(af[mi][0], af[mi][1], af[mi][2], af[mi][3], A0 + aoff[mi][ks]);
#pragma unroll
            for (int nj = 0; nj < 2; ++nj)
                ldsm_x4(bf[nj][0], bf[nj][1], bf[nj][2], bf[nj][3], Bb0 + boff[nj][ks]);
#pragma unroll
            for (int mi = 0; mi < 4; ++mi)
#pragma unroll
                for (int n8 = 0; n8 < 4; ++n8)
                    mma16816(acc[mi][n8], af[mi], &bf[n8 >> 1][(n8 & 1) * 2]);
        }

        if ((st & 15) == 15) {
            // tile epilogue: exp, row/col partial sums
            const int tt = (st >> 4) & 3;
            float colpart[8];
#pragma unroll
            for (int i = 0; i < 8; ++i) colpart[i] = 0.f;
#pragma unroll
            for (int mi = 0; mi < 4; ++mi)
#pragma unroll
                for (int n8 = 0; n8 < 4; ++n8)
#pragma unroll
                    for (int e = 0; e < 4; ++e) {
                        float ex = fast_exp2(acc[mi][n8][e]);   // A scaled by log2e
                        rowpart[mi * 2 + (e >> 1)] += ex;
                        colpart[n8 * 2 + (e & 1)] += ex;
                        acc[mi][n8][e] = 0.f;
                    }
#pragma unroll
            for (int off = 4; off < 32; off <<= 1)
#pragma unroll
                for (int i = 0; i < 8; ++i)
                    colpart[i] += __shfl_xor_sync(0xffffffffu, colpart[i], off);
            if (lane < 4) {
                const int tb = tt * 64 + wn * 32;
#pragma unroll
                for (int i = 0; i < 8; ++i)
                    atomicAdd(&s_colsum[tb + (i >> 1) * 8 + (i & 1) + lane * 2], colpart[i]);
            }
            if ((st & 63) == 63) {
                // strip end: flush rowpart
                const int strip = st >> 6;
#pragma unroll
                for (int off = 1; off < 4; off <<= 1)
#pragma unroll
                    for (int i = 0; i < 8; ++i)
                        rowpart[i] += __shfl_xor_sync(0xffffffffu, rowpart[i], off);
                if ((lane & 3) == 0) {
#pragma unroll
                    for (int i = 0; i < 8; ++i) {
                        int v = strip * 256 + wm * 64 + (i >> 1) * 16 + (i & 1) * 8 + (lane >> 2);
                        atomicAdd(&s_rowsum[v], rowpart[i]);
                    }
                }
#pragma unroll
                for (int i = 0; i < 8; ++i) rowpart[i] = 0.f;
            }
        }

        uint32_t t;
        t = A0;  A0 = A1;   A1 = A2;   A2 = t;
        t = Bb0; Bb0 = Bb1; Bb1 = Bb2; Bb2 = t;
    }
    __syncthreads();

    // flush rowsum to global; colsum -> 0.5 * sum(log) scalar
    atomicAdd(&g_rowsum[bp * 512 + tid], s_rowsum[tid]);
    atomicAdd(&g_rowsum[bp * 512 + tid + 256], s_rowsum[tid + 256]);

    float lc = logf(s_colsum[tid & 255]);
    if (tid >= 256) lc = 0.f;
    lc = warp_reduce_sum(lc);
    if (lane == 0) s_red[warp] = lc;
    __syncthreads();
    if (tid == 0) {
        float tot = 0.f;
#pragma unroll
        for (int w = 0; w < 8; ++w) tot += s_red[w];
        atomicAdd(&g_acc[bp], 0.5f * tot);
    }
}

// ---------------------------------------------------------------------------
// Kernel 3: clip_reduce. clip[bp] = (0.5*sum log rowsum + g_acc - g_diag)/512
// ---------------------------------------------------------------------------
__global__ void clip_reduce_kernel() {
    const int bp = blockIdx.x, tid = threadIdx.x;   // 128 threads
    float s = 0.f;
#pragma unroll
    for (int i = 0; i < 4; ++i) s += logf(g_rowsum[bp * 512 + tid + i * 128]);
    s = warp_reduce_sum(s);
    __shared__ float sr[4];
    if ((tid & 31) == 0) sr[tid >> 5] = s;
    __syncthreads();
    if (tid == 0) {
        float tot = sr[0] + sr[1] + sr[2] + sr[3];
        g_clip[bp] = (0.5f * tot + g_acc[bp] - g_diag[bp]) * (1.0f / 512.0f);
    }
}

// ---------------------------------------------------------------------------
// Kernel 4: finalize. loss = mean((output-clip)^2); acc; preds broadcast.
// ---------------------------------------------------------------------------
__global__ void finalize_kernel(const float* __restrict__ output,
                                float* __restrict__ out, int out_size) {
    __shared__ float s_sq[8];
    __shared__ int s_pred[16];
    __shared__ int s_match;
    const int tid = threadIdx.x;
    const int lane = tid & 31, warp = tid >> 5;
    if (tid == 0) s_match = 0;
    __syncthreads();

    float d = output[tid] - g_clip[tid];
    float sq = warp_reduce_sum(d * d);
    if (lane == 0) s_sq[warp] = sq;

    if (tid < 16) {
        int b = tid;
        float bo = output[b * 16], bc = g_clip[b * 16];
        int po = 0, pcidx = 0;
#pragma unroll
        for (int c = 1; c < 16; ++c) {
            float o = output[b * 16 + c];
            if (o < bo) { bo = o; po = c; }
            float cl = g_clip[b * 16 + c];
            if (cl < bc) { bc = cl; pcidx = c; }
        }
        s_pred[b] = po;
        if (po == pcidx) atomicAdd(&s_match, 1);
    }
    __syncthreads();

    if (tid == 0) {
        float tot = 0.f;
#pragma unroll
        for (int w = 0; w < 8; ++w) tot += s_sq[w];
        if (out_size > 0) out[0] = tot * (1.0f / 256.0f);
        if (out_size > 1) out[1] = (float)s_match * (100.0f / 16.0f);
    }
    for (int idx = tid; idx < 8192; idx += 256) {
        int b = idx >> 9;
        if (idx + 2 < out_size) out[idx + 2] = (float)s_pred[b];
    }
}

// ---------------------------------------------------------------------------
extern "C" void kernel_launch(void* const* d_in, const int* in_sizes, int n_in,
                              void* d_out, int out_size) {
    const float* output = (const float*)d_in[0];        // (B, C)
    const float* text   = (const float*)d_in[1];        // (B, S, C, D)
    const float* vis    = (const float*)d_in[2];        // (B, S, D)
    float* out = (float*)d_out;

    cudaFuncSetAttribute(clip_gemm_kernel, cudaFuncAttributeMaxDynamicSharedMemorySize, DYN_BYTES);

    norm_vis_kernel<<<(B_ * S_) / 8, 256>>>(vis);
    clip_gemm_kernel<<<2 * B_ * C_, 256, DYN_BYTES>>>(text);
    clip_reduce_kernel<<<B_ * C_, 128>>>();
    finalize_kernel<<<1, 256>>>(output, out, out_size);
}

// round 14
// speedup vs baseline: 2.3832x; 1.1242x over previous
#include <cuda_runtime.h>
#include <cuda_bf16.h>
#include <cstdint>

// Problem constants
constexpr int B_ = 16, S_ = 512, C_ = 16, D_ = 512;
constexpr float LOG2E = 1.4426950408889634f;
constexpr float LN2   = 0.6931471805599453f;

// Scratch (device globals: allocation-free per harness rules)
__device__ __nv_bfloat16 g_vn[B_ * S_ * D_];          // normalized vis * log2e, bf16 (8 MB)
__device__ __nv_bfloat16 g_tn[B_ * C_ * S_ * D_];     // normalized text, (B,C,S,D), bf16 (128 MB)
__device__ float g_rowsum[B_ * C_ * S_];               // per-(b,p) rowsum over v
__device__ float g_acc[B_ * C_];                       // 0.5 * sum log colsum (partial)
__device__ float g_diag[B_ * C_];                      // sum of diagonal cosines
__device__ float g_clip[B_ * C_];                      // clip_loss per (b, prompt)

#define DEVFN __device__ __forceinline__

DEVFN float warp_reduce_sum(float v) {
#pragma unroll
    for (int o = 16; o; o >>= 1) v += __shfl_xor_sync(0xffffffffu, v, o);
    return v;
}

DEVFN uint32_t smem_u32(const void* p) { return (uint32_t)__cvta_generic_to_shared(p); }
DEVFN float fast_exp2(float x) { float y; asm("ex2.approx.f32 %0, %1;" : "=f"(y) : "f"(x)); return y; }

DEVFN void cp_async16(uint32_t saddr, const void* gptr) {
    asm volatile("cp.async.cg.shared.global [%0], [%1], 16;" :: "r"(saddr), "l"(gptr));
}
#define CP_COMMIT() asm volatile("cp.async.commit_group;" ::: "memory")
#define CP_WAIT1()  asm volatile("cp.async.wait_group 1;" ::: "memory")
#define CP_WAIT0()  asm volatile("cp.async.wait_group 0;" ::: "memory")

DEVFN void ldsm_x4(uint32_t& r0, uint32_t& r1, uint32_t& r2, uint32_t& r3, uint32_t addr) {
    asm volatile("ldmatrix.sync.aligned.m8n8.x4.shared.b16 {%0,%1,%2,%3}, [%4];"
                 : "=r"(r0), "=r"(r1), "=r"(r2), "=r"(r3) : "r"(addr));
}

DEVFN void mma16816(float* c, const uint32_t* a, const uint32_t* b) {
    asm volatile("mma.sync.aligned.m16n8k16.row.col.f32.bf16.bf16.f32 "
                 "{%0,%1,%2,%3}, {%4,%5,%6,%7}, {%8,%9}, {%0,%1,%2,%3};"
                 : "+f"(c[0]), "+f"(c[1]), "+f"(c[2]), "+f"(c[3])
                 : "r"(a[0]), "r"(a[1]), "r"(a[2]), "r"(a[3]), "r"(b[0]), "r"(b[1]));
}

// swizzle: 64B rows, 4x16B chunks; phys_chunk = kb ^ ((row>>1)&3)
DEVFN int swz(int row, int kb) { return kb ^ ((row >> 1) & 3); }

// ---------------------------------------------------------------------------
// Kernel 1: normalize vis (B,S,D) -> g_vn bf16 scaled by log2e; zero scratch.
// ---------------------------------------------------------------------------
__global__ void norm_vis_kernel(const float* __restrict__ vis) {
    const int tid = threadIdx.x;
    const int gtid = blockIdx.x * 256 + tid;
    if (gtid < B_ * C_ * S_) g_rowsum[gtid] = 0.f;
    if (gtid < B_ * C_) { g_acc[gtid] = 0.f; g_diag[gtid] = 0.f; }

    int row = blockIdx.x * 8 + (tid >> 5);
    int lane = tid & 31;
    const float4* src = reinterpret_cast<const float4*>(vis + (size_t)row * D_);
    float4 v[4];
    float ss = 0.f;
#pragma unroll
    for (int j = 0; j < 4; ++j) {
        v[j] = src[lane + 32 * j];
        ss += v[j].x * v[j].x + v[j].y * v[j].y + v[j].z * v[j].z + v[j].w * v[j].w;
    }
    ss = warp_reduce_sum(ss);
    float inv = LOG2E / fmaxf(sqrtf(ss), 1e-8f);
    __nv_bfloat162* dst = reinterpret_cast<__nv_bfloat162*>(g_vn + (size_t)row * D_);
#pragma unroll
    for (int j = 0; j < 4; ++j) {
        int c = lane + 32 * j;
        dst[2 * c]     = __floats2bfloat162_rn(v[j].x * inv, v[j].y * inv);
        dst[2 * c + 1] = __floats2bfloat162_rn(v[j].z * inv, v[j].w * inv);
    }
}

// ---------------------------------------------------------------------------
// Kernel 2: GEMM + fused text-normalization prologue + exp/row/col sums.
// Grid 1024: (b,p) x text-QUARTER (128 rows). Each block OWNS its 128 text
// rows: prologue normalizes them fp32->bf16 into g_tn (+ diagonal dots);
// __syncthreads makes stores visible to this block's own cp.async reads.
// Mainloop: 512 vis rows (2 strips of 256) x 128 text cols (2 tiles of 64),
// 64 K32 stages, 3-stage cp.async ring, warp layout 4(m) x 2(n), 2 CTAs/SM.
// Finer tiles smooth the tail wave: 1024 = 3*296 + 136, tail CTAs run solo
// per SM at full HMMA rate.
// ---------------------------------------------------------------------------
constexpr uint32_t SA_BYTES = 16384;   // 256 rows x 64B (K32, SW)
constexpr uint32_t SB_BYTES = 4096;    // 64 rows x 64B
constexpr uint32_t OFF_A   = 0;        // 3 stages
constexpr uint32_t OFF_B   = 49152;    // 3 stages
constexpr uint32_t OFF_ROW = 61440;    // 512 f32
constexpr uint32_t OFF_COL = 63488;    // 128 f32
constexpr uint32_t OFF_RED = 64000;    // 8 f32
constexpr uint32_t DYN_BYTES = 64032 + 1024;

extern __shared__ char dynsmem[];

__global__ __launch_bounds__(256, 2) void clip_gemm_kernel(const float* __restrict__ txt) {
    const int tid = threadIdx.x, lane = tid & 31, warp = tid >> 5;
    const int wm = warp & 3;        // rows wm*64
    const int wn = warp >> 2;       // cols wn*32
    const int bid = blockIdx.x;
    const int bp = bid >> 2;        // b*16 + p
    const int q  = bid & 3;         // text-row quarter (128 rows)
    const int b = bp >> 4, p = bp & 15;

    const char* Agc = reinterpret_cast<const char*>(g_vn + (size_t)b * (S_ * D_));
    const char* Bgc = reinterpret_cast<const char*>(g_tn + (size_t)bp * (S_ * D_)
                                                    + (size_t)q * 128 * D_);

    const uint32_t raw = smem_u32(dynsmem);
    const uint32_t sbase = (raw + 1023u) & ~1023u;
    char* gb = dynsmem + (sbase - raw);
    float* s_rowsum = (float*)(gb + OFF_ROW);
    float* s_colsum = (float*)(gb + OFF_COL);
    float* s_red    = (float*)(gb + OFF_RED);

    s_rowsum[tid] = 0.f; s_rowsum[tid + 256] = 0.f;
    s_colsum[tid & 127] = 0.f;

    // ---- Prologue: normalize this block's 128 text rows (fp32 -> bf16) ----
    {
        float diag_acc = 0.f;
#pragma unroll 1
        for (int i = 0; i < 16; ++i) {
            int sl = warp * 16 + i;                    // local text row 0..127
            int s = q * 128 + sl;                      // sequence position
            const float4* src = reinterpret_cast<const float4*>(
                txt + ((size_t)((b * S_ + s) * C_) + p) * D_);
            float4 v[4];
            float ss = 0.f;
#pragma unroll
            for (int j = 0; j < 4; ++j) {
                v[j] = src[lane + 32 * j];
                ss += v[j].x * v[j].x + v[j].y * v[j].y + v[j].z * v[j].z + v[j].w * v[j].w;
            }
            ss = warp_reduce_sum(ss);
            float inv = 1.f / fmaxf(sqrtf(ss), 1e-8f);

            const __nv_bfloat162* vrow =
                reinterpret_cast<const __nv_bfloat162*>(g_vn + (size_t)(b * S_ + s) * D_);
            float dot = 0.f;
            __nv_bfloat162* dst = reinterpret_cast<__nv_bfloat162*>(
                g_tn + ((size_t)bp * S_ + s) * D_);
#pragma unroll
            for (int j = 0; j < 4; ++j) {
                int cc = lane + 32 * j;
                float x0 = v[j].x * inv, x1 = v[j].y * inv;
                float x2 = v[j].z * inv, x3 = v[j].w * inv;
                float2 a0 = __bfloat1622float2(vrow[2 * cc]);
                float2 a1 = __bfloat1622float2(vrow[2 * cc + 1]);
                dot += a0.x * x0 + a0.y * x1 + a1.x * x2 + a1.y * x3;
                dst[2 * cc]     = __floats2bfloat162_rn(x0, x1);
                dst[2 * cc + 1] = __floats2bfloat162_rn(x2, x3);
            }
            diag_acc += dot;   // (g_vn carries LOG2E; rescale below)
        }
        diag_acc = warp_reduce_sum(diag_acc);
        if (lane == 0) atomicAdd(&g_diag[bp], diag_acc * LN2);
    }
    __syncthreads();   // text rows + smem zeros visible before cp.async reads

    // ---- Per-thread cp.async offsets. A: 4 chunks of 16B; B: 1 chunk. ----
    uint32_t aG[4], aD[4];
#pragma unroll
    for (int j = 0; j < 4; ++j) {
        int row = (tid >> 2) + 64 * j;
        int kb = tid & 3;
        aG[j] = (uint32_t)(row * 1024 + kb * 16);
        aD[j] = (uint32_t)((row * 32 + swz(row, kb) * 8) * 2);
    }
    const int rowb = tid >> 2, kbb = tid & 3;
    const uint32_t bG = (uint32_t)(rowb * 1024 + kbb * 16);
    const uint32_t bD = (uint32_t)((rowb * 32 + swz(rowb, kbb) * 8) * 2);

    // ldmatrix byte offsets within a stage
    uint32_t aoff[4][2], boff[2][2];
    {
        int r16 = lane & 15;
        int koff = lane >> 4;
#pragma unroll
        for (int mi = 0; mi < 4; ++mi) {
            int r = wm * 64 + mi * 16 + r16;
#pragma unroll
            for (int ks = 0; ks < 2; ++ks) {
                int chk = ks * 2 + koff;
                aoff[mi][ks] = (uint32_t)((r * 32 + swz(r, chk) * 8) * 2);
            }
        }
        int rb8 = (lane & 7) + ((lane >> 4) << 3);
        int kob = (lane >> 3) & 1;
#pragma unroll
        for (int nj = 0; nj < 2; ++nj) {
            int r = wn * 32 + nj * 16 + rb8;
#pragma unroll
            for (int ks = 0; ks < 2; ++ks) {
                int chk = ks * 2 + kob;
                boff[nj][ks] = (uint32_t)((r * 32 + swz(r, chk) * 8) * 2);
            }
        }
    }

    uint32_t A0 = sbase + OFF_A,  A1 = A0 + SA_BYTES,  A2 = A1 + SA_BYTES;
    uint32_t Bb0 = sbase + OFF_B, Bb1 = Bb0 + SB_BYTES, Bb2 = Bb1 + SB_BYTES;

    // stage st (0..63) -> strip = st>>5, tt = (st>>4)&1, kk = st&15
    auto load_stage = [&](int st, uint32_t sA, uint32_t sB) {
        const char* Ap = Agc + (st >> 5) * 262144 + (st & 15) * 64;
        const char* Bp = Bgc + ((st >> 4) & 1) * 65536 + (st & 15) * 64;
#pragma unroll
        for (int j = 0; j < 4; ++j) cp_async16(sA + aD[j], Ap + aG[j]);
        cp_async16(sB + bD, Bp + bG);
    };

    float acc[4][4][4];
#pragma unroll
    for (int mi = 0; mi < 4; ++mi)
#pragma unroll
        for (int nj = 0; nj < 4; ++nj)
#pragma unroll
            for (int e = 0; e < 4; ++e) acc[mi][nj][e] = 0.f;
    float rowpart[8];
#pragma unroll
    for (int i = 0; i < 8; ++i) rowpart[i] = 0.f;

    // prologue loads
    load_stage(0, A0, Bb0); CP_COMMIT();
    load_stage(1, A1, Bb1); CP_COMMIT();

#pragma unroll 1
    for (int st = 0; st < 64; ++st) {
        if (st < 63) { CP_WAIT1(); } else { CP_WAIT0(); }
        __syncthreads();
        if (st + 2 < 64) { load_stage(st + 2, A2, Bb2); CP_COMMIT(); }

        // compute stage st (buffers A0/Bb0)
#pragma unroll
        for (int ks = 0; ks < 2; ++ks) {
            uint32_t af[4][4], bf[2][4];
#pragma unroll
            for (int mi = 0; mi < 4; ++mi)
                ldsm_x4(af[mi][0], af[mi][1], af[mi][2], af[mi][3], A0 + aoff[mi][ks]);
#pragma unroll
            for (int nj = 0; nj < 2; ++nj)
                ldsm_x4(bf[nj][0], bf[nj][1], bf[nj][2], bf[nj][3], Bb0 + boff[nj][ks]);
#pragma unroll
            for (int mi = 0; mi < 4; ++mi)
#pragma unroll
                for (int n8 = 0; n8 < 4; ++n8)
                    mma16816(acc[mi][n8], af[mi], &bf[n8 >> 1][(n8 & 1) * 2]);
        }

        if ((st & 15) == 15) {
            // tile epilogue: exp, row/col partial sums
            const int tt = (st >> 4) & 1;
            float colpart[8];
#pragma unroll
            for (int i = 0; i < 8; ++i) colpart[i] = 0.f;
#pragma unroll
            for (int mi = 0; mi < 4; ++mi)
#pragma unroll
                for (int n8 = 0; n8 < 4; ++n8)
#pragma unroll
                    for (int e = 0; e < 4; ++e) {
                        float ex = fast_exp2(acc[mi][n8][e]);   // A scaled by log2e
                        rowpart[mi * 2 + (e >> 1)] += ex;
                        colpart[n8 * 2 + (e & 1)] += ex;
                        acc[mi][n8][e] = 0.f;
                    }
#pragma unroll
            for (int off = 4; off < 32; off <<= 1)
#pragma unroll
                for (int i = 0; i < 8; ++i)
                    colpart[i] += __shfl_xor_sync(0xffffffffu, colpart[i], off);
            if (lane < 4) {
                const int tb = tt * 64 + wn * 32;
#pragma unroll
                for (int i = 0; i < 8; ++i)
                    atomicAdd(&s_colsum[tb + (i >> 1) * 8 + (i & 1) + lane * 2], colpart[i]);
            }
            if ((st & 31) == 31) {
                // strip end: flush rowpart
                const int strip = st >> 5;
#pragma unroll
                for (int off = 1; off < 4; off <<= 1)
#pragma unroll
                    for (int i = 0; i < 8; ++i)
                        rowpart[i] += __shfl_xor_sync(0xffffffffu, rowpart[i], off);
                if ((lane & 3) == 0) {
#pragma unroll
                    for (int i = 0; i < 8; ++i) {
                        int v = strip * 256 + wm * 64 + (i >> 1) * 16 + (i & 1) * 8 + (lane >> 2);
                        atomicAdd(&s_rowsum[v], rowpart[i]);
                    }
                }
#pragma unroll
                for (int i = 0; i < 8; ++i) rowpart[i] = 0.f;
            }
        }

        uint32_t t;
        t = A0;  A0 = A1;   A1 = A2;   A2 = t;
        t = Bb0; Bb0 = Bb1; Bb1 = Bb2; Bb2 = t;
    }
    __syncthreads();

    // flush rowsum to global; colsum -> 0.5 * sum(log) scalar
    atomicAdd(&g_rowsum[bp * 512 + tid], s_rowsum[tid]);
    atomicAdd(&g_rowsum[bp * 512 + tid + 256], s_rowsum[tid + 256]);

    float lc = (tid < 128) ? logf(s_colsum[tid]) : 0.f;
    lc = warp_reduce_sum(lc);
    if (lane == 0) s_red[warp] = lc;
    __syncthreads();
    if (tid == 0) {
        float tot = 0.f;
#pragma unroll
        for (int w = 0; w < 8; ++w) tot += s_red[w];
        atomicAdd(&g_acc[bp], 0.5f * tot);
    }
}

// ---------------------------------------------------------------------------
// Kernel 3: clip_reduce. clip[bp] = (0.5*sum log rowsum + g_acc - g_diag)/512
// ---------------------------------------------------------------------------
__global__ void clip_reduce_kernel() {
    const int bp = blockIdx.x, tid = threadIdx.x;   // 128 threads
    float s = 0.f;
#pragma unroll
    for (int i = 0; i < 4; ++i) s += logf(g_rowsum[bp * 512 + tid + i * 128]);
    s = warp_reduce_sum(s);
    __shared__ float sr[4];
    if ((tid & 31) == 0) sr[tid >> 5] = s;
    __syncthreads();
    if (tid == 0) {
        float tot = sr[0] + sr[1] + sr[2] + sr[3];
        g_clip[bp] = (0.5f * tot + g_acc[bp] - g_diag[bp]) * (1.0f / 512.0f);
    }
}

// ---------------------------------------------------------------------------
// Kernel 4: finalize. loss = mean((output-clip)^2); acc; preds broadcast.
// ---------------------------------------------------------------------------
__global__ void finalize_kernel(const float* __restrict__ output,
                                float* __restrict__ out, int out_size) {
    __shared__ float s_sq[8];
    __shared__ int s_pred[16];
    __shared__ int s_match;
    const int tid = threadIdx.x;
    const int lane = tid & 31, warp = tid >> 5;
    if (tid == 0) s_match = 0;
    __syncthreads();

    float d = output[tid] - g_clip[tid];
    float sq = warp_reduce_sum(d * d);
    if (lane == 0) s_sq[warp] = sq;

    if (tid < 16) {
        int b = tid;
        float bo = output[b * 16], bc = g_clip[b * 16];
        int po = 0, pcidx = 0;
#pragma unroll
        for (int c = 1; c < 16; ++c) {
            float o = output[b * 16 + c];
            if (o < bo) { bo = o; po = c; }
            float cl = g_clip[b * 16 + c];
            if (cl < bc) { bc = cl; pcidx = c; }
        }
        s_pred[b] = po;
        if (po == pcidx) atomicAdd(&s_match, 1);
    }
    __syncthreads();

    if (tid == 0) {
        float tot = 0.f;
#pragma unroll
        for (int w = 0; w < 8; ++w) tot += s_sq[w];
        if (out_size > 0) out[0] = tot * (1.0f / 256.0f);
        if (out_size > 1) out[1] = (float)s_match * (100.0f / 16.0f);
    }
    for (int idx = tid; idx < 8192; idx += 256) {
        int b = idx >> 9;
        if (idx + 2 < out_size) out[idx + 2] = (float)s_pred[b];
    }
}

// ---------------------------------------------------------------------------
extern "C" void kernel_launch(void* const* d_in, const int* in_sizes, int n_in,
                              void* d_out, int out_size) {
    const float* output = (const float*)d_in[0];        // (B, C)
    const float* text   = (const float*)d_in[1];        // (B, S, C, D)
    const float* vis    = (const float*)d_in[2];        // (B, S, D)
    float* out = (float*)d_out;

    cudaFuncSetAttribute(clip_gemm_kernel, cudaFuncAttributeMaxDynamicSharedMemorySize, DYN_BYTES);

    norm_vis_kernel<<<(B_ * S_) / 8, 256>>>(vis);
    clip_gemm_kernel<<<4 * B_ * C_, 256, DYN_BYTES>>>(text);
    clip_reduce_kernel<<<B_ * C_, 128>>>();
    finalize_kernel<<<1, 256>>>(output, out, out_size);
}